// round 3
// baseline (speedup 1.0000x reference)
#include <cuda_runtime.h>

// VectorQuantizerEMA on GB300 (sm_103a)
// z: [16, 256, 4096] f32, codebook: [1024, 256] f32 -> out [16, 256, 4096] f32
// Fused fp32 distance-GEMM (packed fma.rn.f32x2) + argmin + gather.

#define NB    16
#define DDIM  256
#define TLEN  4096
#define KCB   1024
#define TM    128   // tokens per block
#define TKC   128   // codes per chunk
#define DSUB  32    // d-slice per cs tile
#define NTHR  256
#define NTILES 64   // 8 code chunks * 8 d-slices
#define CS_STRIDE 128
#define SMEM_FLOATS 45440   // 181760 bytes

__device__ float g_csq[KCB];

__global__ void csq_kernel(const float* __restrict__ cb) {
    int wid = threadIdx.x >> 5, lane = threadIdx.x & 31;
    int code = blockIdx.x * 8 + wid;
    const float* row = cb + (size_t)code * DDIM;
    float s = 0.f;
    #pragma unroll
    for (int d = 0; d < DDIM; d += 32) { float v = row[d + lane]; s = fmaf(v, v, s); }
    #pragma unroll
    for (int o = 16; o; o >>= 1) s += __shfl_xor_sync(0xffffffffu, s, o);
    if (lane == 0) g_csq[code] = s;
}

__device__ __forceinline__ unsigned long long pk2(float x) {
    unsigned long long r;
    asm("mov.b64 %0, {%1, %1};" : "=l"(r) : "f"(x));
    return r;
}

__device__ __forceinline__ void fma2(unsigned long long& d, unsigned long long a,
                                     unsigned long long b) {
    asm("fma.rn.f32x2 %0, %1, %2, %0;" : "+l"(d) : "l"(a), "l"(b));
}

__device__ __forceinline__ void upk(unsigned long long v, float& lo, float& hi) {
    asm("mov.b64 {%0, %1}, %2;" : "=f"(lo), "=f"(hi) : "l"(v));
}

__global__ __launch_bounds__(NTHR, 1)
void vq_kernel(const float* __restrict__ z, const float* __restrict__ cb,
               float* __restrict__ out) {
    extern __shared__ float sm[];
    float* zs    = sm;                     // 32896 floats (compute uses 32768; gather uses 128*257)
    float* cs    = sm + 32896;             // 2 * 32*128 = 8192 floats
    float* redv  = cs + 8192;              // 16*128
    int*   redi  = (int*)(redv + 2048);    // 16*128
    float* bestv = (float*)(redi + 2048);  // 128
    int*   besti = (int*)(bestv + 128);    // 128

    const int tid = threadIdx.x;
    const int tx  = tid & 15;              // token sub-block
    const int ty  = tid >> 4;              // code sub-block
    const int bid = blockIdx.x;
    const int batch = bid >> 5;
    const int t0 = (bid & 31) << 7;
    const float* zb = z + ((size_t)batch * DDIM) * TLEN + t0;

    if (tid < TM) { bestv[tid] = 3.4028235e38f; besti[tid] = 0; }

    // ---- load z tile: zs[d*128 + t], 8192 float4, coalesced ----
    #pragma unroll
    for (int r = 0; r < 32; r++) {
        int j  = tid + NTHR * r;
        int d  = j >> 5;
        int t4 = (j & 31) << 2;
        *(float4*)(zs + d * TM + t4) = *(const float4*)(zb + (size_t)d * TLEN + t4);
    }

    const int code0 = tid & 31;            // conflict-free transposed STS mapping
    const int dq0   = (tid >> 5) << 2;

    // ---- cs tile 0 (kc=0, ds=0) ----
    {
        #pragma unroll
        for (int s = 0; s < 4; s++) {
            int code = code0 + 32 * s;
            float4 v = *(const float4*)(cb + (size_t)code * DDIM + dq0);
            cs[(dq0 + 0) * CS_STRIDE + code] = v.x;
            cs[(dq0 + 1) * CS_STRIDE + code] = v.y;
            cs[(dq0 + 2) * CS_STRIDE + code] = v.z;
            cs[(dq0 + 3) * CS_STRIDE + code] = v.w;
        }
    }
    __syncthreads();

    unsigned long long acc[8][4];
    #pragma unroll
    for (int i = 0; i < 8; i++)
        #pragma unroll
        for (int j = 0; j < 4; j++) acc[i][j] = 0ull;

    for (int kc = 0; kc < 8; kc++) {
        for (int ds = 0; ds < 8; ds++) {
            const int t = kc * 8 + ds;
            const bool hasNext = (t + 1) < NTILES;
            float4 pf0, pf1, pf2, pf3;
            if (hasNext) {
                const int nt = t + 1;
                const int nkc = nt >> 3, nds = nt & 7;
                const float* gp = cb + (size_t)(nkc * TKC + code0) * DDIM + nds * DSUB + dq0;
                pf0 = *(const float4*)(gp);
                pf1 = *(const float4*)(gp + 32 * DDIM);
                pf2 = *(const float4*)(gp + 64 * DDIM);
                pf3 = *(const float4*)(gp + 96 * DDIM);
            }
            const float* cc = cs + (t & 1) * (DSUB * CS_STRIDE);
            const float* za = zs + ds * DSUB * TM + tx * 8;
            #pragma unroll 4
            for (int dd = 0; dd < DSUB; dd++) {
                float4 a0 = *(const float4*)(za + dd * TM);
                float4 a1 = *(const float4*)(za + dd * TM + 4);
                unsigned long long ap[8];
                ap[0] = pk2(a0.x); ap[1] = pk2(a0.y); ap[2] = pk2(a0.z); ap[3] = pk2(a0.w);
                ap[4] = pk2(a1.x); ap[5] = pk2(a1.y); ap[6] = pk2(a1.z); ap[7] = pk2(a1.w);
                const ulonglong2* bp = (const ulonglong2*)(cc + dd * CS_STRIDE + ty * 8);
                ulonglong2 bx = bp[0];
                ulonglong2 by = bp[1];
                unsigned long long bb[4] = { bx.x, bx.y, by.x, by.y };
                #pragma unroll
                for (int i = 0; i < 8; i++)
                    #pragma unroll
                    for (int j = 0; j < 4; j++)
                        fma2(acc[i][j], ap[i], bb[j]);
            }
            if (hasNext) {
                float* cw = cs + ((t + 1) & 1) * (DSUB * CS_STRIDE);
                cw[(dq0 + 0) * CS_STRIDE + code0 +  0] = pf0.x;
                cw[(dq0 + 1) * CS_STRIDE + code0 +  0] = pf0.y;
                cw[(dq0 + 2) * CS_STRIDE + code0 +  0] = pf0.z;
                cw[(dq0 + 3) * CS_STRIDE + code0 +  0] = pf0.w;
                cw[(dq0 + 0) * CS_STRIDE + code0 + 32] = pf1.x;
                cw[(dq0 + 1) * CS_STRIDE + code0 + 32] = pf1.y;
                cw[(dq0 + 2) * CS_STRIDE + code0 + 32] = pf1.z;
                cw[(dq0 + 3) * CS_STRIDE + code0 + 32] = pf1.w;
                cw[(dq0 + 0) * CS_STRIDE + code0 + 64] = pf2.x;
                cw[(dq0 + 1) * CS_STRIDE + code0 + 64] = pf2.y;
                cw[(dq0 + 2) * CS_STRIDE + code0 + 64] = pf2.z;
                cw[(dq0 + 3) * CS_STRIDE + code0 + 64] = pf2.w;
                cw[(dq0 + 0) * CS_STRIDE + code0 + 96] = pf3.x;
                cw[(dq0 + 1) * CS_STRIDE + code0 + 96] = pf3.y;
                cw[(dq0 + 2) * CS_STRIDE + code0 + 96] = pf3.z;
                cw[(dq0 + 3) * CS_STRIDE + code0 + 96] = pf3.w;
            }
            __syncthreads();
        }

        // ---- per-chunk argmin epilogue: score = csq[k] - 2*dot (z^2 invariant) ----
        #pragma unroll
        for (int i = 0; i < 8; i++) {
            float mv = 3.4028235e38f; int mi = 0;
            #pragma unroll
            for (int j = 0; j < 4; j++) {
                const int k0 = kc * TKC + ty * 8 + j * 2;
                float lo, hi; upk(acc[i][j], lo, hi);
                float s0 = fmaf(-2.f, lo, g_csq[k0]);
                float s1 = fmaf(-2.f, hi, g_csq[k0 + 1]);
                if (s0 < mv) { mv = s0; mi = k0; }
                if (s1 < mv) { mv = s1; mi = k0 + 1; }
                acc[i][j] = 0ull;
            }
            redv[ty * TM + tx * 8 + i] = mv;
            redi[ty * TM + tx * 8 + i] = mi;
        }
        __syncthreads();
        if (tid < TM) {
            float bv = bestv[tid]; int bi = besti[tid];
            #pragma unroll
            for (int y = 0; y < 16; y++) {
                float v = redv[y * TM + tid];
                int  ix = redi[y * TM + tid];
                if (v < bv || (v == bv && ix < bi)) { bv = v; bi = ix; }
            }
            bestv[tid] = bv; besti[tid] = bi;
        }
        __syncthreads();
    }

    // ---- gather: stage codebook rows via smem so reads AND writes coalesce ----
    // zs reused as [t][257] (padded: conflict-free transposed reads)
    for (int j = tid; j < TM * 64; j += NTHR) {
        int t  = j >> 6;
        int f4 = j & 63;
        float4 v = *(const float4*)(cb + (size_t)besti[t] * DDIM + (f4 << 2));
        float* p = zs + t * 257 + (f4 << 2);
        p[0] = v.x; p[1] = v.y; p[2] = v.z; p[3] = v.w;
    }
    __syncthreads();
    float* ob = out + ((size_t)batch * DDIM) * TLEN + t0;
    for (int i = tid; i < DDIM * TM; i += NTHR) {
        int d = i >> 7;
        int t = i & 127;
        ob[(size_t)d * TLEN + t] = zs[t * 257 + d];
    }
}

extern "C" void kernel_launch(void* const* d_in, const int* in_sizes, int n_in,
                              void* d_out, int out_size) {
    const float* z  = (const float*)d_in[0];
    const float* cb = (const float*)d_in[1];
    float* out = (float*)d_out;
    cudaFuncSetAttribute(vq_kernel, cudaFuncAttributeMaxDynamicSharedMemorySize,
                         SMEM_FLOATS * 4);
    csq_kernel<<<KCB / 8, 256>>>(cb);
    vq_kernel<<<512, NTHR, SMEM_FLOATS * 4>>>(z, cb, out);
}

// round 5
// speedup vs baseline: 2.6470x; 2.6470x over previous
#include <cuda_runtime.h>
#include <cuda_bf16.h>
#include <cstdint>

#define DDIM 256
#define TLEN 4096
#define KCB  1024
#define TM   128
#define CAP  48
#define TAU  0.15f

// K2 smem byte offsets
#define ZS_OFF   0        // z bf16 [128 tok][512B] swizzled
#define CB_OFF   65536    // codebook chunk double buffer 2x64KB
#define CSQ_OFF  196608   // 1024 floats
#define SCNT_OFF 200704   // 128 ints
#define SMEM2    201216
#define SMEM3    132096   // K3: 128*257 floats + 128 ints

__device__ __nv_bfloat16 g_cb16[KCB * DDIM];
__device__ float g_csq[KCB];
__device__ int   g_cand[65536 * CAP];
__device__ int   g_cnt[65536];

// ---------------- helpers ----------------
__device__ __forceinline__ uint32_t smem_u32(const void* p) {
    uint32_t a;
    asm("{ .reg .u64 t; cvta.to.shared.u64 t, %1; cvt.u32.u64 %0, t; }" : "=r"(a) : "l"(p));
    return a;
}
__device__ __forceinline__ uint32_t pkbf2(float lo, float hi) {
    __nv_bfloat162 h = __floats2bfloat162_rn(lo, hi);
    return *(uint32_t*)&h;
}
__device__ __forceinline__ void ldsm_x4(uint32_t* r, uint32_t a) {
    asm volatile("ldmatrix.sync.aligned.m8n8.x4.shared.b16 {%0,%1,%2,%3}, [%4];"
        : "=r"(r[0]), "=r"(r[1]), "=r"(r[2]), "=r"(r[3]) : "r"(a));
}
__device__ __forceinline__ void stsm_x2t(uint32_t a, uint32_t r0, uint32_t r1) {
    asm volatile("stmatrix.sync.aligned.m8n8.x2.trans.shared.b16 [%0], {%1,%2};"
        :: "r"(a), "r"(r0), "r"(r1));
}
__device__ __forceinline__ void mma16816(float* c, const uint32_t* a,
                                         uint32_t b0, uint32_t b1) {
    asm volatile("mma.sync.aligned.m16n8k16.row.col.f32.bf16.bf16.f32 "
        "{%0,%1,%2,%3}, {%4,%5,%6,%7}, {%8,%9}, {%0,%1,%2,%3};"
        : "+f"(c[0]), "+f"(c[1]), "+f"(c[2]), "+f"(c[3])
        : "r"(a[0]), "r"(a[1]), "r"(a[2]), "r"(a[3]), "r"(b0), "r"(b1));
}
__device__ __forceinline__ void cp16(uint32_t dst, const void* src) {
    asm volatile("cp.async.cg.shared.global [%0], [%1], 16;" :: "r"(dst), "l"(src));
}
#define CP_COMMIT() asm volatile("cp.async.commit_group;" ::: "memory")
#define CP_WAIT(n)  asm volatile("cp.async.wait_group %0;" :: "n"(n) : "memory")

// ---------------- kernel 1: codebook -> bf16, csq ----------------
__global__ void prep_kernel(const float* __restrict__ cb) {
    int tid = threadIdx.x, wid = tid >> 5, lane = tid & 31;
    int code = blockIdx.x * 8 + wid;
    const float* row = cb + (size_t)code * DDIM;
    float s = 0.f;
    #pragma unroll
    for (int d = lane; d < DDIM; d += 32) {
        float v = row[d];
        s = fmaf(v, v, s);
        g_cb16[code * DDIM + d] = __float2bfloat16(v);
    }
    #pragma unroll
    for (int o = 16; o; o >>= 1) s += __shfl_xor_sync(0xffffffffu, s, o);
    if (!lane) g_csq[code] = s;
}

// ---------------- kernel 2: HMMA bf16 GEMM + candidate prune ----------------
__device__ __forceinline__ void load_chunk_async(uint32_t cbbase, int chunk, int tid) {
    const char* src = (const char*)g_cb16 + (size_t)chunk * 65536;
    #pragma unroll
    for (int i = 0; i < 16; i++) {
        int g = tid + 256 * i;                 // 16B granule 0..4095
        int code = g >> 5, col = g & 31;
        uint32_t dst = cbbase + code * 512 + (uint32_t)((col ^ (code & 7)) << 4);
        cp16(dst, src + (size_t)g * 16);
    }
}

__global__ __launch_bounds__(256, 1)
void vq_main(const float* __restrict__ z) {
    extern __shared__ char sm[];
    uint32_t smb = smem_u32(sm);
    const uint32_t zs_b = smb + ZS_OFF;
    const uint32_t cb_b = smb + CB_OFF;
    float* csq_s = (float*)(sm + CSQ_OFF);
    int*   scnt  = (int*)(sm + SCNT_OFF);

    const int tid = threadIdx.x;
    const int wid = tid >> 5;
    const int lane = tid & 31;
    const int batch = blockIdx.x >> 5;
    const int t0 = (blockIdx.x & 31) << 7;
    const int nbase = batch * TLEN + t0;

    // start codebook chunk loads immediately (overlap with transpose)
    load_chunk_async(cb_b, 0, tid);            CP_COMMIT();
    load_chunk_async(cb_b + 65536, 1, tid);    CP_COMMIT();

    if (tid < 128) scnt[tid] = 0;
    #pragma unroll
    for (int i = tid; i < KCB; i += 256) csq_s[i] = g_csq[i];

    // ---- transpose z -> zs (warp w handles its own 16 tokens) ----
    {
        const float* zb = z + (size_t)batch * DDIM * TLEN + t0 + wid * 16;
        const int drow = lane >> 2;            // 0..7
        const int tp = (lane & 3) * 2;         // token pair offset 0,2,4,6
        const int tl = lane & 15;              // dest-row lane
        const uint32_t stb = zs_b + (uint32_t)(wid * 16 + tl) * 512;
        const uint32_t tswz = (uint32_t)(tl & 7);
        #pragma unroll
        for (int dt = 0; dt < 32; dt++) {
            const float* p = zb + (size_t)(dt * 8 + drow) * TLEN + tp;
            float2 v0 = *(const float2*)p;
            float2 v1 = *(const float2*)(p + 8);
            uint32_t r0 = pkbf2(v0.x, v0.y);
            uint32_t r1 = pkbf2(v1.x, v1.y);
            stsm_x2t(stb + ((((uint32_t)dt) ^ tswz) << 4), r0, r1);
        }
    }
    __syncwarp();

    // ---- load token B-fragments (held in regs for the whole kernel) ----
    uint32_t bfr[2][16][2];
    #pragma unroll
    for (int nt = 0; nt < 2; nt++) {
        const int trow = wid * 16 + nt * 8 + (lane & 7);
        const int m = lane >> 3;               // matrix id 0..3
        const uint32_t tswz = (uint32_t)(trow & 7);
        const uint32_t tb = zs_b + (uint32_t)trow * 512;
        #pragma unroll
        for (int kp = 0; kp < 8; kp++) {
            const int kk = kp * 2 + (m >> 1);
            const int h = m & 1;
            uint32_t ad = tb + ((((uint32_t)(kk * 2 + h)) ^ tswz) << 4);
            uint32_t r[4];
            ldsm_x4(r, ad);
            bfr[nt][kp * 2][0]     = r[0];
            bfr[nt][kp * 2][1]     = r[1];
            bfr[nt][kp * 2 + 1][0] = r[2];
            bfr[nt][kp * 2 + 1][1] = r[3];
        }
    }

    float rm[2][2] = {{3.4e38f, 3.4e38f}, {3.4e38f, 3.4e38f}};
    const int arow7 = (lane & 7) + ((lane & 8) ? 8 : 0);
    const uint32_t ah = (uint32_t)(lane >> 4);

    for (int c = 0; c < 8; c++) {
        if (c < 7) CP_WAIT(1); else CP_WAIT(0);
        __syncthreads();
        const uint32_t cbc = cb_b + (uint32_t)(c & 1) * 65536;

        for (int mb = 0; mb < 8; mb++) {
            float acc[2][2][4];
            #pragma unroll
            for (int n = 0; n < 2; n++)
                #pragma unroll
                for (int p = 0; p < 2; p++)
                    #pragma unroll
                    for (int r = 0; r < 4; r++) acc[n][p][r] = 0.f;

            const int arow = mb * 16 + arow7;
            const uint32_t abase = cbc + (uint32_t)arow * 512;
            const uint32_t aswz = (uint32_t)(arow & 7);
            #pragma unroll
            for (int k = 0; k < 16; k++) {
                uint32_t ar[4];
                ldsm_x4(ar, abase + ((((uint32_t)(k * 2) | ah) ^ aswz) << 4));
                mma16816(acc[0][k & 1], ar, bfr[0][k][0], bfr[0][k][1]);
                mma16816(acc[1][k & 1], ar, bfr[1][k][0], bfr[1][k][1]);
            }

            const int cA = c * 128 + mb * 16 + (lane >> 2);
            const int cB = cA + 8;
            const float qA = csq_s[cA];
            const float qB = csq_s[cB];
            float ss[2][4];
            #pragma unroll
            for (int nt = 0; nt < 2; nt++) {
                ss[nt][0] = fmaf(-2.f, acc[nt][0][0] + acc[nt][1][0], qA);
                ss[nt][1] = fmaf(-2.f, acc[nt][0][1] + acc[nt][1][1], qA);
                ss[nt][2] = fmaf(-2.f, acc[nt][0][2] + acc[nt][1][2], qB);
                ss[nt][3] = fmaf(-2.f, acc[nt][0][3] + acc[nt][1][3], qB);
                rm[nt][0] = fminf(rm[nt][0], fminf(ss[nt][0], ss[nt][2]));
                rm[nt][1] = fminf(rm[nt][1], fminf(ss[nt][1], ss[nt][3]));
            }
            // sync running mins across the 8 lanes sharing each token column
            #pragma unroll
            for (int off = 4; off <= 16; off <<= 1) {
                #pragma unroll
                for (int nt = 0; nt < 2; nt++) {
                    rm[nt][0] = fminf(rm[nt][0], __shfl_xor_sync(0xffffffffu, rm[nt][0], off));
                    rm[nt][1] = fminf(rm[nt][1], __shfl_xor_sync(0xffffffffu, rm[nt][1], off));
                }
            }
            // collect candidates within TAU of running min
            #pragma unroll
            for (int nt = 0; nt < 2; nt++) {
                const int tb0 = wid * 16 + nt * 8 + (lane & 3) * 2;
                const float th0 = rm[nt][0] + TAU;
                const float th1 = rm[nt][1] + TAU;
                if (ss[nt][0] < th0) {
                    int p = atomicAdd(&scnt[tb0], 1);
                    if (p < CAP) g_cand[(size_t)(nbase + tb0) * CAP + p] = cA;
                }
                if (ss[nt][2] < th0) {
                    int p = atomicAdd(&scnt[tb0], 1);
                    if (p < CAP) g_cand[(size_t)(nbase + tb0) * CAP + p] = cB;
                }
                if (ss[nt][1] < th1) {
                    int p = atomicAdd(&scnt[tb0 + 1], 1);
                    if (p < CAP) g_cand[(size_t)(nbase + tb0 + 1) * CAP + p] = cA;
                }
                if (ss[nt][3] < th1) {
                    int p = atomicAdd(&scnt[tb0 + 1], 1);
                    if (p < CAP) g_cand[(size_t)(nbase + tb0 + 1) * CAP + p] = cB;
                }
            }
        }
        __syncthreads();
        if (c + 2 < 8) { load_chunk_async(cbc, c + 2, tid); CP_COMMIT(); }
    }
    __syncthreads();
    if (tid < 128) {
        int v = scnt[tid];
        g_cnt[nbase + tid] = (v < CAP) ? v : CAP;
    }
}

// ---------------- kernel 3: exact fp32 rescore + gather ----------------
__global__ __launch_bounds__(256, 1)
void vq_rescore(const float* __restrict__ z, const float* __restrict__ cb,
                float* __restrict__ out) {
    extern __shared__ float sms[];
    float* zs = sms;                       // [128][257]
    int* besti = (int*)(sms + TM * 257);   // 128 ints
    const int tid = threadIdx.x;
    const int batch = blockIdx.x >> 5;
    const int t0 = (blockIdx.x & 31) << 7;
    const float* zb = z + (size_t)batch * DDIM * TLEN + t0;

    #pragma unroll
    for (int r = 0; r < 32; r++) {
        int j = tid + 256 * r;
        int d = j >> 5, t4 = (j & 31) << 2;
        float4 v = *(const float4*)(zb + (size_t)d * TLEN + t4);
        zs[(t4 + 0) * 257 + d] = v.x;
        zs[(t4 + 1) * 257 + d] = v.y;
        zs[(t4 + 2) * 257 + d] = v.z;
        zs[(t4 + 3) * 257 + d] = v.w;
    }
    __syncthreads();

    const int warp = tid >> 5, lane = tid & 31;
    for (int tt = 0; tt < 16; tt++) {
        int tok = warp * 16 + tt;
        int n = batch * TLEN + t0 + tok;
        float zr[8];
        #pragma unroll
        for (int q = 0; q < 8; q++) zr[q] = zs[tok * 257 + lane + 32 * q];
        int cnt = g_cnt[n];
        float bv = 3.4028235e38f; int bi = 0;
        for (int j = 0; j < cnt; j++) {
            int k = g_cand[(size_t)n * CAP + j];
            const float* cr = cb + (size_t)k * DDIM + lane;
            float dot = 0.f;
            #pragma unroll
            for (int q = 0; q < 8; q++) dot = fmaf(zr[q], cr[32 * q], dot);
            #pragma unroll
            for (int o = 16; o; o >>= 1) dot += __shfl_xor_sync(0xffffffffu, dot, o);
            float s = fmaf(-2.f, dot, g_csq[k]);
            if (s < bv || (s == bv && k < bi)) { bv = s; bi = k; }
        }
        if (!lane) besti[tok] = bi;
    }
    __syncthreads();

    for (int j = tid; j < TM * 64; j += 256) {
        int t = j >> 6, f4 = (j & 63) << 2;
        float4 v = *(const float4*)(cb + (size_t)besti[t] * DDIM + f4);
        float* p = zs + t * 257 + f4;
        p[0] = v.x; p[1] = v.y; p[2] = v.z; p[3] = v.w;
    }
    __syncthreads();
    float* ob = out + (size_t)batch * DDIM * TLEN + t0;
    for (int i = tid; i < DDIM * TM; i += 256) {
        int d = i >> 7, t = i & 127;
        ob[(size_t)d * TLEN + t] = zs[t * 257 + d];
    }
}

extern "C" void kernel_launch(void* const* d_in, const int* in_sizes, int n_in,
                              void* d_out, int out_size) {
    const float* z  = (const float*)d_in[0];
    const float* cb = (const float*)d_in[1];
    float* out = (float*)d_out;
    cudaFuncSetAttribute(vq_main, cudaFuncAttributeMaxDynamicSharedMemorySize, SMEM2);
    cudaFuncSetAttribute(vq_rescore, cudaFuncAttributeMaxDynamicSharedMemorySize, SMEM3);
    prep_kernel<<<KCB / 8, 256>>>(cb);
    vq_main<<<512, 256, SMEM2>>>(z);
    vq_rescore<<<512, 256, SMEM3>>>(z, cb, out);
}

// round 6
// speedup vs baseline: 2.7685x; 1.0459x over previous
#include <cuda_runtime.h>
#include <cuda_bf16.h>
#include <cstdint>

#define DDIM 256
#define TLEN 4096
#define KCB  1024
#define TM   128
#define CAP  48
#define TAU  0.15f

// fused kernel smem byte offsets
#define ZS_OFF    0        // z bf16 [128 tok][512B] swizzled  (64KB)
#define CB_OFF    65536    // codebook chunk double buffer 2x64KB
#define CSQ_OFF   196608   // 1024 floats
#define SCNT_OFF  200704   // 128 ints
#define CAND_OFF  201216   // 128*48 ints = 24576B
#define BESTI_OFF 225792   // 128 ints
#define SMEMF     226304

__device__ __nv_bfloat16 g_cb16[KCB * DDIM];
__device__ float g_csq[KCB];

// ---------------- helpers ----------------
__device__ __forceinline__ uint32_t smem_u32(const void* p) {
    uint32_t a;
    asm("{ .reg .u64 t; cvta.to.shared.u64 t, %1; cvt.u32.u64 %0, t; }" : "=r"(a) : "l"(p));
    return a;
}
__device__ __forceinline__ uint32_t pkbf2(float lo, float hi) {
    __nv_bfloat162 h = __floats2bfloat162_rn(lo, hi);
    return *(uint32_t*)&h;
}
__device__ __forceinline__ void ldsm_x4(uint32_t* r, uint32_t a) {
    asm volatile("ldmatrix.sync.aligned.m8n8.x4.shared.b16 {%0,%1,%2,%3}, [%4];"
        : "=r"(r[0]), "=r"(r[1]), "=r"(r[2]), "=r"(r[3]) : "r"(a));
}
__device__ __forceinline__ void stsm_x2t(uint32_t a, uint32_t r0, uint32_t r1) {
    asm volatile("stmatrix.sync.aligned.m8n8.x2.trans.shared.b16 [%0], {%1,%2};"
        :: "r"(a), "r"(r0), "r"(r1));
}
__device__ __forceinline__ void mma16816(float* c, const uint32_t* a,
                                         uint32_t b0, uint32_t b1) {
    asm volatile("mma.sync.aligned.m16n8k16.row.col.f32.bf16.bf16.f32 "
        "{%0,%1,%2,%3}, {%4,%5,%6,%7}, {%8,%9}, {%0,%1,%2,%3};"
        : "+f"(c[0]), "+f"(c[1]), "+f"(c[2]), "+f"(c[3])
        : "r"(a[0]), "r"(a[1]), "r"(a[2]), "r"(a[3]), "r"(b0), "r"(b1));
}
__device__ __forceinline__ void cp16(uint32_t dst, const void* src) {
    asm volatile("cp.async.cg.shared.global [%0], [%1], 16;" :: "r"(dst), "l"(src));
}
#define CP_COMMIT() asm volatile("cp.async.commit_group;" ::: "memory")
#define CP_WAIT(n)  asm volatile("cp.async.wait_group %0;" :: "n"(n) : "memory")

// ---------------- kernel 1: codebook -> bf16, csq ----------------
__global__ void prep_kernel(const float* __restrict__ cb) {
    int tid = threadIdx.x, wid = tid >> 5, lane = tid & 31;
    int code = blockIdx.x * 8 + wid;
    const float* row = cb + (size_t)code * DDIM;
    float s = 0.f;
    #pragma unroll
    for (int d = lane; d < DDIM; d += 32) {
        float v = row[d];
        s = fmaf(v, v, s);
        g_cb16[code * DDIM + d] = __float2bfloat16(v);
    }
    #pragma unroll
    for (int o = 16; o; o >>= 1) s += __shfl_xor_sync(0xffffffffu, s, o);
    if (!lane) g_csq[code] = s;
}

// ---------------- fused: HMMA prune + exact fp32 rescore + gather ----------------
__device__ __forceinline__ void load_chunk_async(uint32_t cbbase, int chunk, int tid) {
    const char* src = (const char*)g_cb16 + (size_t)chunk * 65536;
    #pragma unroll
    for (int i = 0; i < 16; i++) {
        int g = tid + 256 * i;                 // 16B granule 0..4095
        int code = g >> 5, col = g & 31;
        uint32_t dst = cbbase + code * 512 + (uint32_t)((col ^ (code & 7)) << 4);
        cp16(dst, src + (size_t)g * 16);
    }
}

__global__ __launch_bounds__(256, 1)
void vq_fused(const float* __restrict__ z, const float* __restrict__ cb,
              float* __restrict__ out) {
    extern __shared__ char sm[];
    uint32_t smb = smem_u32(sm);
    const uint32_t zs_b = smb + ZS_OFF;
    const uint32_t cb_b = smb + CB_OFF;
    float* csq_s = (float*)(sm + CSQ_OFF);
    int*   scnt  = (int*)(sm + SCNT_OFF);
    int*   cand  = (int*)(sm + CAND_OFF);
    int*   besti = (int*)(sm + BESTI_OFF);

    const int tid = threadIdx.x;
    const int wid = tid >> 5;
    const int lane = tid & 31;
    const int batch = blockIdx.x >> 5;
    const int t0 = (blockIdx.x & 31) << 7;

    // start codebook chunk loads immediately
    load_chunk_async(cb_b, 0, tid);            CP_COMMIT();
    load_chunk_async(cb_b + 65536, 1, tid);    CP_COMMIT();

    if (tid < 128) scnt[tid] = 0;
    #pragma unroll
    for (int i = tid; i < KCB; i += 256) csq_s[i] = g_csq[i];

    // ---- transpose z -> zs (warp w handles its own 16 tokens) ----
    {
        const float* zb = z + (size_t)batch * DDIM * TLEN + t0 + wid * 16;
        const int drow = lane >> 2;
        const int tp = (lane & 3) * 2;
        const int tl = lane & 15;
        const uint32_t stb = zs_b + (uint32_t)(wid * 16 + tl) * 512;
        const uint32_t tswz = (uint32_t)(tl & 7);
        #pragma unroll
        for (int dt = 0; dt < 32; dt++) {
            const float* p = zb + (size_t)(dt * 8 + drow) * TLEN + tp;
            float2 v0 = *(const float2*)p;
            float2 v1 = *(const float2*)(p + 8);
            stsm_x2t(stb + ((((uint32_t)dt) ^ tswz) << 4),
                     pkbf2(v0.x, v0.y), pkbf2(v1.x, v1.y));
        }
    }
    __syncwarp();

    // ---- token B-fragments, register resident for the whole chunk loop ----
    uint32_t bfr[2][16][2];
    #pragma unroll
    for (int nt = 0; nt < 2; nt++) {
        const int trow = wid * 16 + nt * 8 + (lane & 7);
        const int m = lane >> 3;
        const uint32_t tswz = (uint32_t)(trow & 7);
        const uint32_t tb = zs_b + (uint32_t)trow * 512;
        #pragma unroll
        for (int kp = 0; kp < 8; kp++) {
            const int kk = kp * 2 + (m >> 1);
            const int h = m & 1;
            uint32_t r[4];
            ldsm_x4(r, tb + ((((uint32_t)(kk * 2 + h)) ^ tswz) << 4));
            bfr[nt][kp * 2][0]     = r[0];
            bfr[nt][kp * 2][1]     = r[1];
            bfr[nt][kp * 2 + 1][0] = r[2];
            bfr[nt][kp * 2 + 1][1] = r[3];
        }
    }

    float rm[2][2] = {{3.4e38f, 3.4e38f}, {3.4e38f, 3.4e38f}};
    const int arow7 = (lane & 7) + ((lane & 8) ? 8 : 0);
    const uint32_t ah = (uint32_t)(lane >> 4);

    for (int c = 0; c < 8; c++) {
        if (c < 7) CP_WAIT(1); else CP_WAIT(0);
        __syncthreads();
        const uint32_t cbc = cb_b + (uint32_t)(c & 1) * 65536;

        for (int mb = 0; mb < 8; mb++) {
            float acc[2][2][4];
            #pragma unroll
            for (int n = 0; n < 2; n++)
                #pragma unroll
                for (int p = 0; p < 2; p++)
                    #pragma unroll
                    for (int r = 0; r < 4; r++) acc[n][p][r] = 0.f;

            const int arow = mb * 16 + arow7;
            const uint32_t abase = cbc + (uint32_t)arow * 512;
            const uint32_t aswz = (uint32_t)(arow & 7);
            #pragma unroll
            for (int k = 0; k < 16; k++) {
                uint32_t ar[4];
                ldsm_x4(ar, abase + ((((uint32_t)(k * 2) | ah) ^ aswz) << 4));
                mma16816(acc[0][k & 1], ar, bfr[0][k][0], bfr[0][k][1]);
                mma16816(acc[1][k & 1], ar, bfr[1][k][0], bfr[1][k][1]);
            }

            const int cA = c * 128 + mb * 16 + (lane >> 2);
            const int cB = cA + 8;
            const float qA = csq_s[cA];
            const float qB = csq_s[cB];
            float ss[2][4];
            #pragma unroll
            for (int nt = 0; nt < 2; nt++) {
                ss[nt][0] = fmaf(-2.f, acc[nt][0][0] + acc[nt][1][0], qA);
                ss[nt][1] = fmaf(-2.f, acc[nt][0][1] + acc[nt][1][1], qA);
                ss[nt][2] = fmaf(-2.f, acc[nt][0][2] + acc[nt][1][2], qB);
                ss[nt][3] = fmaf(-2.f, acc[nt][0][3] + acc[nt][1][3], qB);
                rm[nt][0] = fminf(rm[nt][0], fminf(ss[nt][0], ss[nt][2]));
                rm[nt][1] = fminf(rm[nt][1], fminf(ss[nt][1], ss[nt][3]));
            }
            // rotating-stride min diffusion: 1 shfl per value per mb.
            // rm stays an upper bound of the true running min -> threshold
            // remains a valid superset bound (collection still provably safe).
            {
                const int off = 4 << (mb % 3);   // 4, 8, 16, 4, ...
                #pragma unroll
                for (int nt = 0; nt < 2; nt++) {
                    rm[nt][0] = fminf(rm[nt][0], __shfl_xor_sync(0xffffffffu, rm[nt][0], off));
                    rm[nt][1] = fminf(rm[nt][1], __shfl_xor_sync(0xffffffffu, rm[nt][1], off));
                }
            }
            // collect candidates within TAU of (upper bound of) running min
            #pragma unroll
            for (int nt = 0; nt < 2; nt++) {
                const int tb0 = wid * 16 + nt * 8 + (lane & 3) * 2;
                const float th0 = rm[nt][0] + TAU;
                const float th1 = rm[nt][1] + TAU;
                if (ss[nt][0] < th0) {
                    int p = atomicAdd(&scnt[tb0], 1);
                    if (p < CAP) cand[tb0 * CAP + p] = cA;
                }
                if (ss[nt][2] < th0) {
                    int p = atomicAdd(&scnt[tb0], 1);
                    if (p < CAP) cand[tb0 * CAP + p] = cB;
                }
                if (ss[nt][1] < th1) {
                    int p = atomicAdd(&scnt[tb0 + 1], 1);
                    if (p < CAP) cand[tb0 + 1 > 127 ? 0 : (tb0 + 1) * CAP + p] = cA;
                }
                if (ss[nt][3] < th1) {
                    int p = atomicAdd(&scnt[tb0 + 1], 1);
                    if (p < CAP) cand[(tb0 + 1) * CAP + p] = cB;
                }
            }
        }
        __syncthreads();
        if (c + 2 < 8) { load_chunk_async(cbc, c + 2, tid); CP_COMMIT(); }
    }
    __syncthreads();

    // ================= fused exact fp32 rescore =================
    // reuse smem [0, 131584) for z fp32 staged [128][257]
    float* zs = (float*)sm;
    {
        const float* zb = z + (size_t)batch * DDIM * TLEN + t0;
        #pragma unroll
        for (int r = 0; r < 32; r++) {
            int j = tid + 256 * r;
            int d = j >> 5, t4 = (j & 31) << 2;
            float4 v = *(const float4*)(zb + (size_t)d * TLEN + t4);
            zs[(t4 + 0) * 257 + d] = v.x;
            zs[(t4 + 1) * 257 + d] = v.y;
            zs[(t4 + 2) * 257 + d] = v.z;
            zs[(t4 + 3) * 257 + d] = v.w;
        }
    }
    __syncthreads();

    for (int tt = 0; tt < 16; tt++) {
        const int tok = wid * 16 + tt;
        int cnt = scnt[tok]; if (cnt > CAP) cnt = CAP;
        float zr[8];
        #pragma unroll
        for (int q = 0; q < 8; q++) zr[q] = zs[tok * 257 + lane + 32 * q];
        float bv = 3.4028235e38f; int bi = 0;
        int j = 0;
        for (; j + 1 < cnt; j += 2) {
            const int k0 = cand[tok * CAP + j];
            const int k1 = cand[tok * CAP + j + 1];
            const float* c0 = cb + (size_t)k0 * DDIM + lane;
            const float* c1 = cb + (size_t)k1 * DDIM + lane;
            float d0 = 0.f, d1 = 0.f;
            #pragma unroll
            for (int q = 0; q < 8; q++) {
                d0 = fmaf(zr[q], c0[32 * q], d0);
                d1 = fmaf(zr[q], c1[32 * q], d1);
            }
            #pragma unroll
            for (int o = 16; o; o >>= 1) {
                d0 += __shfl_xor_sync(0xffffffffu, d0, o);
                d1 += __shfl_xor_sync(0xffffffffu, d1, o);
            }
            float s0 = fmaf(-2.f, d0, csq_s[k0]);
            float s1 = fmaf(-2.f, d1, csq_s[k1]);
            if (s0 < bv || (s0 == bv && k0 < bi)) { bv = s0; bi = k0; }
            if (s1 < bv || (s1 == bv && k1 < bi)) { bv = s1; bi = k1; }
        }
        if (j < cnt) {
            const int k0 = cand[tok * CAP + j];
            const float* c0 = cb + (size_t)k0 * DDIM + lane;
            float d0 = 0.f;
            #pragma unroll
            for (int q = 0; q < 8; q++) d0 = fmaf(zr[q], c0[32 * q], d0);
            #pragma unroll
            for (int o = 16; o; o >>= 1) d0 += __shfl_xor_sync(0xffffffffu, d0, o);
            float s0 = fmaf(-2.f, d0, csq_s[k0]);
            if (s0 < bv || (s0 == bv && k0 < bi)) { bv = s0; bi = k0; }
        }
        if (!lane) besti[tok] = bi;
    }
    __syncthreads();

    // gather codebook rows through smem so reads AND writes coalesce
    for (int j = tid; j < TM * 64; j += 256) {
        int t = j >> 6, f4 = (j & 63) << 2;
        float4 v = *(const float4*)(cb + (size_t)besti[t] * DDIM + f4);
        float* p = zs + t * 257 + f4;
        p[0] = v.x; p[1] = v.y; p[2] = v.z; p[3] = v.w;
    }
    __syncthreads();
    float* ob = out + (size_t)batch * DDIM * TLEN + t0;
    for (int i = tid; i < DDIM * TM; i += 256) {
        int d = i >> 7, t = i & 127;
        ob[(size_t)d * TLEN + t] = zs[t * 257 + d];
    }
}

extern "C" void kernel_launch(void* const* d_in, const int* in_sizes, int n_in,
                              void* d_out, int out_size) {
    const float* z  = (const float*)d_in[0];
    const float* cb = (const float*)d_in[1];
    float* out = (float*)d_out;
    cudaFuncSetAttribute(vq_fused, cudaFuncAttributeMaxDynamicSharedMemorySize, SMEMF);
    prep_kernel<<<KCB / 8, 256>>>(cb);
    vq_fused<<<512, 256, SMEMF>>>(z, cb, out);
}

// round 7
// speedup vs baseline: 4.1213x; 1.4886x over previous
#include <cuda_runtime.h>
#include <cuda_bf16.h>
#include <cstdint>

#define DDIM 256
#define TLEN 4096
#define KCB  1024
#define TM   128
#define CAP  32
#define TAU  0.15f
#define NCH  16      // chunks of 64 codes

// fused kernel smem byte offsets (85.5 KB total -> 2 CTAs/SM)
#define REGION_OFF 0        // 66048B: zs [128tok][512B] during setup; then cb double buf 2x32KB; then rescore staging
#define CSQ_OFF    66048    // 1024 floats
#define SCNT_OFF   70144    // 128 ints
#define CAND_OFF   70656    // 128*32 ints = 16384B
#define BESTI_OFF  87040    // 128 ints
#define SMEMF      87552

__device__ __nv_bfloat16 g_cb16[KCB * DDIM];
__device__ float g_csq[KCB];

// ---------------- helpers ----------------
__device__ __forceinline__ uint32_t smem_u32(const void* p) {
    uint32_t a;
    asm("{ .reg .u64 t; cvta.to.shared.u64 t, %1; cvt.u32.u64 %0, t; }" : "=r"(a) : "l"(p));
    return a;
}
__device__ __forceinline__ uint32_t pkbf2(float lo, float hi) {
    __nv_bfloat162 h = __floats2bfloat162_rn(lo, hi);
    return *(uint32_t*)&h;
}
__device__ __forceinline__ void ldsm_x4(uint32_t* r, uint32_t a) {
    asm volatile("ldmatrix.sync.aligned.m8n8.x4.shared.b16 {%0,%1,%2,%3}, [%4];"
        : "=r"(r[0]), "=r"(r[1]), "=r"(r[2]), "=r"(r[3]) : "r"(a));
}
__device__ __forceinline__ void stsm_x2t(uint32_t a, uint32_t r0, uint32_t r1) {
    asm volatile("stmatrix.sync.aligned.m8n8.x2.trans.shared.b16 [%0], {%1,%2};"
        :: "r"(a), "r"(r0), "r"(r1));
}
__device__ __forceinline__ void mma16816(float* c, const uint32_t* a,
                                         uint32_t b0, uint32_t b1) {
    asm volatile("mma.sync.aligned.m16n8k16.row.col.f32.bf16.bf16.f32 "
        "{%0,%1,%2,%3}, {%4,%5,%6,%7}, {%8,%9}, {%0,%1,%2,%3};"
        : "+f"(c[0]), "+f"(c[1]), "+f"(c[2]), "+f"(c[3])
        : "r"(a[0]), "r"(a[1]), "r"(a[2]), "r"(a[3]), "r"(b0), "r"(b1));
}
__device__ __forceinline__ void cp16(uint32_t dst, const void* src) {
    asm volatile("cp.async.cg.shared.global [%0], [%1], 16;" :: "r"(dst), "l"(src));
}
#define CP_COMMIT() asm volatile("cp.async.commit_group;" ::: "memory")
#define CP_WAIT(n)  asm volatile("cp.async.wait_group %0;" :: "n"(n) : "memory")

// ---------------- kernel 1: codebook -> bf16, csq ----------------
__global__ void prep_kernel(const float* __restrict__ cb) {
    int tid = threadIdx.x, wid = tid >> 5, lane = tid & 31;
    int code = blockIdx.x * 8 + wid;
    const float* row = cb + (size_t)code * DDIM;
    float s = 0.f;
    #pragma unroll
    for (int d = lane; d < DDIM; d += 32) {
        float v = row[d];
        s = fmaf(v, v, s);
        g_cb16[code * DDIM + d] = __float2bfloat16(v);
    }
    #pragma unroll
    for (int o = 16; o; o >>= 1) s += __shfl_xor_sync(0xffffffffu, s, o);
    if (!lane) g_csq[code] = s;
}

// load 64-code chunk (32KB) into swizzled smem buffer, 8 cp.async per thread
__device__ __forceinline__ void load_chunk_async(uint32_t cbbase, int chunk, int tid) {
    const char* src = (const char*)g_cb16 + (size_t)chunk * 32768;
    #pragma unroll
    for (int i = 0; i < 8; i++) {
        int g = tid + 256 * i;                 // granule 0..2047
        int code = g >> 5, col = g & 31;
        uint32_t dst = cbbase + code * 512 + (uint32_t)((col ^ (code & 7)) << 4);
        cp16(dst, src + (size_t)g * 16);
    }
}

// ---------------- fused: HMMA prune + exact fp32 rescore + gather ----------------
__global__ __launch_bounds__(256, 2)
void vq_fused(const float* __restrict__ z, const float* __restrict__ cb,
              float* __restrict__ out) {
    extern __shared__ char sm[];
    uint32_t smb = smem_u32(sm);
    const uint32_t zs_b = smb + REGION_OFF;
    const uint32_t cb_b = smb + REGION_OFF;        // overlaid on zs
    float* csq_s = (float*)(sm + CSQ_OFF);
    int*   scnt  = (int*)(sm + SCNT_OFF);
    int*   cand  = (int*)(sm + CAND_OFF);
    int*   besti = (int*)(sm + BESTI_OFF);

    const int tid = threadIdx.x;
    const int wid = tid >> 5;
    const int lane = tid & 31;
    const int batch = blockIdx.x >> 5;
    const int t0 = (blockIdx.x & 31) << 7;

    if (tid < 128) scnt[tid] = 0;
    #pragma unroll
    for (int i = tid; i < KCB; i += 256) csq_s[i] = g_csq[i];

    // ---- transpose z -> zs (warp w handles its own 16 tokens) ----
    {
        const float* zb = z + (size_t)batch * DDIM * TLEN + t0 + wid * 16;
        const int drow = lane >> 2;
        const int tp = (lane & 3) * 2;
        const int tl = lane & 15;
        const uint32_t stb = zs_b + (uint32_t)(wid * 16 + tl) * 512;
        const uint32_t tswz = (uint32_t)(tl & 7);
        #pragma unroll
        for (int dt = 0; dt < 32; dt++) {
            const float* p = zb + (size_t)(dt * 8 + drow) * TLEN + tp;
            float2 v0 = *(const float2*)p;
            float2 v1 = *(const float2*)(p + 8);
            stsm_x2t(stb + ((((uint32_t)dt) ^ tswz) << 4),
                     pkbf2(v0.x, v0.y), pkbf2(v1.x, v1.y));
        }
    }
    __syncwarp();

    // ---- token B-fragments, register resident for the whole chunk loop ----
    uint32_t bfr[2][16][2];
    #pragma unroll
    for (int nt = 0; nt < 2; nt++) {
        const int trow = wid * 16 + nt * 8 + (lane & 7);
        const int m = lane >> 3;
        const uint32_t tswz = (uint32_t)(trow & 7);
        const uint32_t tb = zs_b + (uint32_t)trow * 512;
        #pragma unroll
        for (int kp = 0; kp < 8; kp++) {
            const int kk = kp * 2 + (m >> 1);
            const int h = m & 1;
            uint32_t r[4];
            ldsm_x4(r, tb + ((((uint32_t)(kk * 2 + h)) ^ tswz) << 4));
            bfr[nt][kp * 2][0]     = r[0];
            bfr[nt][kp * 2][1]     = r[1];
            bfr[nt][kp * 2 + 1][0] = r[2];
            bfr[nt][kp * 2 + 1][1] = r[3];
        }
    }
    __syncthreads();   // all warps done reading zs; cb buffers may overwrite

    // start codebook chunk pipeline (overlaid region now free)
    load_chunk_async(cb_b, 0, tid);            CP_COMMIT();
    load_chunk_async(cb_b + 32768, 1, tid);    CP_COMMIT();

    float rm[2][2] = {{3.4e38f, 3.4e38f}, {3.4e38f, 3.4e38f}};
    const int arow7 = (lane & 7) + ((lane & 8) ? 8 : 0);
    const uint32_t ah = (uint32_t)(lane >> 4);

    for (int c = 0; c < NCH; c++) {
        if (c < NCH - 1) CP_WAIT(1); else CP_WAIT(0);
        __syncthreads();
        const uint32_t cbc = cb_b + (uint32_t)(c & 1) * 32768;

        #pragma unroll
        for (int mb = 0; mb < 4; mb++) {
            float acc[2][2][4];
            #pragma unroll
            for (int n = 0; n < 2; n++)
                #pragma unroll
                for (int p = 0; p < 2; p++)
                    #pragma unroll
                    for (int r = 0; r < 4; r++) acc[n][p][r] = 0.f;

            const int arow = mb * 16 + arow7;
            const uint32_t abase = cbc + (uint32_t)arow * 512;
            const uint32_t aswz = (uint32_t)(arow & 7);
            #pragma unroll
            for (int k = 0; k < 16; k++) {
                uint32_t ar[4];
                ldsm_x4(ar, abase + ((((uint32_t)(k * 2) | ah) ^ aswz) << 4));
                mma16816(acc[0][k & 1], ar, bfr[0][k][0], bfr[0][k][1]);
                mma16816(acc[1][k & 1], ar, bfr[1][k][0], bfr[1][k][1]);
            }

            const int cA = c * 64 + mb * 16 + (lane >> 2);
            const int cB = cA + 8;
            const float qA = csq_s[cA];
            const float qB = csq_s[cB];
            float ss[2][4];
            #pragma unroll
            for (int nt = 0; nt < 2; nt++) {
                ss[nt][0] = fmaf(-2.f, acc[nt][0][0] + acc[nt][1][0], qA);
                ss[nt][1] = fmaf(-2.f, acc[nt][0][1] + acc[nt][1][1], qA);
                ss[nt][2] = fmaf(-2.f, acc[nt][0][2] + acc[nt][1][2], qB);
                ss[nt][3] = fmaf(-2.f, acc[nt][0][3] + acc[nt][1][3], qB);
                rm[nt][0] = fminf(rm[nt][0], fminf(ss[nt][0], ss[nt][2]));
                rm[nt][1] = fminf(rm[nt][1], fminf(ss[nt][1], ss[nt][3]));
            }
            // rotating-stride min diffusion (rm stays a valid upper bound)
            {
                const int off = 4 << ((c * 4 + mb) % 3);
                #pragma unroll
                for (int nt = 0; nt < 2; nt++) {
                    rm[nt][0] = fminf(rm[nt][0], __shfl_xor_sync(0xffffffffu, rm[nt][0], off));
                    rm[nt][1] = fminf(rm[nt][1], __shfl_xor_sync(0xffffffffu, rm[nt][1], off));
                }
            }
            #pragma unroll
            for (int nt = 0; nt < 2; nt++) {
                const int tb0 = wid * 16 + nt * 8 + (lane & 3) * 2;
                const float th0 = rm[nt][0] + TAU;
                const float th1 = rm[nt][1] + TAU;
                if (ss[nt][0] < th0) {
                    int p = atomicAdd(&scnt[tb0], 1);
                    if (p < CAP) cand[tb0 * CAP + p] = cA;
                }
                if (ss[nt][2] < th0) {
                    int p = atomicAdd(&scnt[tb0], 1);
                    if (p < CAP) cand[tb0 * CAP + p] = cB;
                }
                if (ss[nt][1] < th1) {
                    int p = atomicAdd(&scnt[tb0 + 1], 1);
                    if (p < CAP) cand[(tb0 + 1) * CAP + p] = cA;
                }
                if (ss[nt][3] < th1) {
                    int p = atomicAdd(&scnt[tb0 + 1], 1);
                    if (p < CAP) cand[(tb0 + 1) * CAP + p] = cB;
                }
            }
        }
        __syncthreads();
        if (c + 2 < NCH) { load_chunk_async(cbc, c + 2, tid); CP_COMMIT(); }
    }

    // ================= fused exact fp32 rescore (two 64-token passes) =================
    float* zs = (float*)sm;   // [64][257] fp32 staging per pass
    #pragma unroll 1
    for (int h = 0; h < 2; h++) {
        __syncthreads();
        const float* zb = z + (size_t)batch * DDIM * TLEN + t0 + h * 64;
        #pragma unroll
        for (int r = 0; r < 16; r++) {
            int j = tid + 256 * r;            // 0..4095 float4s
            int d = j >> 4, t4 = (j & 15) << 2;
            float4 v = *(const float4*)(zb + (size_t)d * TLEN + t4);
            zs[(t4 + 0) * 257 + d] = v.x;
            zs[(t4 + 1) * 257 + d] = v.y;
            zs[(t4 + 2) * 257 + d] = v.z;
            zs[(t4 + 3) * 257 + d] = v.w;
        }
        __syncthreads();

        for (int tt = 0; tt < 8; tt++) {
            const int tl = wid * 8 + tt;       // local token 0..63
            const int tok = h * 64 + tl;
            int cnt = scnt[tok]; if (cnt > CAP) cnt = CAP;
            float zr[8];
            #pragma unroll
            for (int q = 0; q < 8; q++) zr[q] = zs[tl * 257 + lane + 32 * q];
            float bv = 3.4028235e38f; int bi = 0;
            int j = 0;
            for (; j + 1 < cnt; j += 2) {
                const int k0 = cand[tok * CAP + j];
                const int k1 = cand[tok * CAP + j + 1];
                const float* c0 = cb + (size_t)k0 * DDIM + lane;
                const float* c1 = cb + (size_t)k1 * DDIM + lane;
                float d0 = 0.f, d1 = 0.f;
                #pragma unroll
                for (int q = 0; q < 8; q++) {
                    d0 = fmaf(zr[q], c0[32 * q], d0);
                    d1 = fmaf(zr[q], c1[32 * q], d1);
                }
                #pragma unroll
                for (int o = 16; o; o >>= 1) {
                    d0 += __shfl_xor_sync(0xffffffffu, d0, o);
                    d1 += __shfl_xor_sync(0xffffffffu, d1, o);
                }
                float s0 = fmaf(-2.f, d0, csq_s[k0]);
                float s1 = fmaf(-2.f, d1, csq_s[k1]);
                if (s0 < bv || (s0 == bv && k0 < bi)) { bv = s0; bi = k0; }
                if (s1 < bv || (s1 == bv && k1 < bi)) { bv = s1; bi = k1; }
            }
            if (j < cnt) {
                const int k0 = cand[tok * CAP + j];
                const float* c0 = cb + (size_t)k0 * DDIM + lane;
                float d0 = 0.f;
                #pragma unroll
                for (int q = 0; q < 8; q++) d0 = fmaf(zr[q], c0[32 * q], d0);
                #pragma unroll
                for (int o = 16; o; o >>= 1) d0 += __shfl_xor_sync(0xffffffffu, d0, o);
                float s0 = fmaf(-2.f, d0, csq_s[k0]);
                if (s0 < bv || (s0 == bv && k0 < bi)) { bv = s0; bi = k0; }
            }
            if (!lane) besti[tok] = bi;
        }
    }

    // ================= gather (two 64-token passes, coalesced both sides) =================
    #pragma unroll 1
    for (int h = 0; h < 2; h++) {
        __syncthreads();
        for (int j = tid; j < 64 * 64; j += 256) {
            int t = j >> 6, f4 = (j & 63) << 2;
            float4 v = *(const float4*)(cb + (size_t)besti[h * 64 + t] * DDIM + f4);
            float* p = zs + t * 257 + f4;
            p[0] = v.x; p[1] = v.y; p[2] = v.z; p[3] = v.w;
        }
        __syncthreads();
        float* ob = out + (size_t)batch * DDIM * TLEN + t0 + h * 64;
        for (int i = tid; i < DDIM * 64; i += 256) {
            int d = i >> 6, t = i & 63;
            ob[(size_t)d * TLEN + t] = zs[t * 257 + d];
        }
    }
}

extern "C" void kernel_launch(void* const* d_in, const int* in_sizes, int n_in,
                              void* d_out, int out_size) {
    const float* z  = (const float*)d_in[0];
    const float* cb = (const float*)d_in[1];
    float* out = (float*)d_out;
    cudaFuncSetAttribute(vq_fused, cudaFuncAttributeMaxDynamicSharedMemorySize, SMEMF);
    prep_kernel<<<KCB / 8, 256>>>(cb);
    vq_fused<<<512, 256, SMEMF>>>(z, cb, out);
}